// round 3
// baseline (speedup 1.0000x reference)
#include <cuda_runtime.h>
#include <cuda_fp16.h>
#include <cstdint>

// ---------------------------------------------------------------------------
// InflateHexToVertex, factored:
//   Z[j,t,b,v] = hex[b,t,:] @ W[j*D:(j+1)*D, :]      (1.6 GFLOP GEMM, fp32 acc)
//   out[b,n,v] = bias[v] + sum_j (idx[n,j] >= 0) * Z[j, idx[n,j], b, v]
//
// Z stored in fp16 (12.6 MB) -> stays L2-resident; halves gather read traffic.
// Output stores use __stcs so the 328 MB write stream doesn't evict Z.
// ---------------------------------------------------------------------------

#define GEMM_MT 128
#define GEMM_NT 64
#define GEMM_K  128
#define GEMM_THREADS 256

// scratch: Z[j][t][b][v]  (3, T<=512, B<=32, V=128) fp16 = 12.6 MB
__device__ __half g_Zh[3 * 512 * 32 * 128];

// --- Z = hex(16384x128) @ W(384x128), fp32 FFMA, fp16 store ------------------
// 128x64 tile, 8x4 microtile per thread, K=128 in one shot.
// SMEM: As[k][m] (transposed A, 64KB) + Bs[k][n] (32KB) = 96KB dynamic.
__global__ void gemm_z(const float* __restrict__ A, const float* __restrict__ W,
                       int M, int T, int B, int V) {
    extern __shared__ float sm[];
    float* As = sm;                      // [k][m]: k*128 + m
    float* Bs = sm + GEMM_K * GEMM_MT;   // [k][n]: k*64  + n

    const int tid = threadIdx.x;
    const int m0 = blockIdx.x * GEMM_MT;
    const int n0 = blockIdx.y * GEMM_NT;
    const int j  = n0 / V;               // which 128-row block of W (0..2)
    const int v0 = n0 - j * V;           // 0 or 64

    // Load A tile transposed into As[k][m] (STS.32 per component, conflict-free).
    #pragma unroll
    for (int it = 0; it < (GEMM_MT * GEMM_K / 4) / GEMM_THREADS; ++it) {  // 16
        int p  = it * GEMM_THREADS + tid;
        int m  = p & (GEMM_MT - 1);
        int k4 = p >> 7;                 // 0..31
        float4 av = make_float4(0.f, 0.f, 0.f, 0.f);
        if (m0 + m < M)
            av = *(const float4*)(A + (size_t)(m0 + m) * GEMM_K + k4 * 4);
        As[(k4 * 4 + 0) * GEMM_MT + m] = av.x;
        As[(k4 * 4 + 1) * GEMM_MT + m] = av.y;
        As[(k4 * 4 + 2) * GEMM_MT + m] = av.z;
        As[(k4 * 4 + 3) * GEMM_MT + m] = av.w;
    }
    // Load B tile: Bs[k][n] = W[j*128 + k][v0 + n]
    #pragma unroll
    for (int it = 0; it < (GEMM_K * GEMM_NT / 4) / GEMM_THREADS; ++it) {  // 8
        int p  = it * GEMM_THREADS + tid;
        int k  = p >> 4;
        int c4 = p & 15;
        *(float4*)(Bs + k * GEMM_NT + c4 * 4) =
            *(const float4*)(W + (size_t)(j * GEMM_K + k) * V + v0 + c4 * 4);
    }
    __syncthreads();

    const int tx = tid & 15;   // n: 4 cols
    const int ty = tid >> 4;   // m: 8 rows

    float acc[8][4];
    #pragma unroll
    for (int i = 0; i < 8; ++i)
        #pragma unroll
        for (int q = 0; q < 4; ++q) acc[i][q] = 0.f;

    #pragma unroll 8
    for (int k = 0; k < GEMM_K; ++k) {
        float4 a0 = *(const float4*)(As + k * GEMM_MT + ty * 8);
        float4 a1 = *(const float4*)(As + k * GEMM_MT + ty * 8 + 4);
        float4 bv = *(const float4*)(Bs + k * GEMM_NT + tx * 4);
        float a[8]  = {a0.x, a0.y, a0.z, a0.w, a1.x, a1.y, a1.z, a1.w};
        float bb[4] = {bv.x, bv.y, bv.z, bv.w};
        #pragma unroll
        for (int i = 0; i < 8; ++i)
            #pragma unroll
            for (int q = 0; q < 4; ++q)
                acc[i][q] += a[i] * bb[q];
    }

    // Convert to fp16 and write Z[j][t][b][v0 + tx*4 ..]
    #pragma unroll
    for (int i = 0; i < 8; ++i) {
        int m = m0 + ty * 8 + i;
        if (m >= M) continue;
        int b = m / T;
        int t = m - b * T;
        __half2 h01 = __floats2half2_rn(acc[i][0], acc[i][1]);
        __half2 h23 = __floats2half2_rn(acc[i][2], acc[i][3]);
        __half2* dst = (__half2*)(g_Zh + (((size_t)j * T + t) * B + b) * 128
                                  + v0 + tx * 4);
        dst[0] = h01;
        dst[1] = h23;
    }
}

// --- out[b,n,:] = bias + sum_j Z[j, idx[n,j], b, :] --------------------------
// One block per vertex n, 512 threads = one (b, v8) item per thread.
// Per (j,b): a warp reads two contiguous 256B fp16 rows from L2-resident Z.
// int64/int32 index detection via warp-ballot on the array head (parallel,
// one L2-broadcast load per lane).
__global__ void gather_out(const int* __restrict__ idxw,
                           const float* __restrict__ bias,
                           float* __restrict__ out, int N, int T, int B) {
    __shared__ int sh_t[3];
    const int n   = blockIdx.x;
    const int tid = threadIdx.x;

    if (tid < 32) {
        // int64 little-endian => every odd word is the sign extension of the
        // preceding word. 32 lanes check 32 pairs in parallel; int32 data with
        // values in [-1,T) fails this with probability ~1.
        int lo = idxw[2 * tid];
        int hi = idxw[2 * tid + 1];
        unsigned ok = __ballot_sync(0xffffffffu, hi == ((lo < 0) ? -1 : 0));
        int s = 1 + (ok == 0xffffffffu);     // word stride per index element
        if (tid < 3) sh_t[tid] = idxw[n * 3 * s + tid * s];
    }
    __syncthreads();
    const int t0 = sh_t[0], t1 = sh_t[1], t2 = sh_t[2];

    const uint4*  Z16 = (const uint4*)g_Zh;   // 16B = 8 halves
    const float4* b4  = (const float4*)bias;

    const int b  = tid >> 4;             // 0..B-1
    const int v8 = tid & 15;             // 8-half chunk within 128-wide row

    float4 accA = __ldg(b4 + v8 * 2);
    float4 accB = __ldg(b4 + v8 * 2 + 1);

    #pragma unroll
    for (int j = 0; j < 3; ++j) {
        int t = (j == 0) ? t0 : (j == 1) ? t1 : t2;
        if (t < 0) continue;
        uint4 z = Z16[(((size_t)j * T + t) * B + b) * 16 + v8];
        float2 f0 = __half22float2(*(__half2*)&z.x);
        float2 f1 = __half22float2(*(__half2*)&z.y);
        float2 f2 = __half22float2(*(__half2*)&z.z);
        float2 f3 = __half22float2(*(__half2*)&z.w);
        accA.x += f0.x; accA.y += f0.y; accA.z += f1.x; accA.w += f1.y;
        accB.x += f2.x; accB.y += f2.y; accB.z += f3.x; accB.w += f3.y;
    }

    float* o = out + ((size_t)b * N + n) * 128 + v8 * 8;
    __stcs((float4*)o, accA);
    __stcs((float4*)(o + 4), accB);
}

extern "C" void kernel_launch(void* const* d_in, const int* in_sizes, int n_in,
                              void* d_out, int out_size) {
    const float* hex  = (const float*)d_in[0];   // (B, T, D) f32
    const int*   idxw = (const int*)d_in[1];     // (N, 3) int32 or int64
    const float* W    = (const float*)d_in[2];   // (3D, V) f32
    const float* bias = (const float*)d_in[3];   // (V,) f32
    float*       out  = (float*)d_out;           // (B, N, V) f32

    const int V      = in_sizes[3];              // 128
    const int threeD = in_sizes[2] / V;          // 384
    const int D      = threeD / 3;               // 128
    const int BT     = in_sizes[0] / D;          // B*T = 16384
    const int N      = in_sizes[1] / 3;          // 20000
    const int B      = out_size / (N * V);       // 32
    const int T      = BT / B;                   // 512

    cudaFuncSetAttribute(gemm_z, cudaFuncAttributeMaxDynamicSharedMemorySize,
                         (GEMM_K * GEMM_MT + GEMM_K * GEMM_NT) * (int)sizeof(float));

    dim3 g1((BT + GEMM_MT - 1) / GEMM_MT, (3 * V) / GEMM_NT);
    gemm_z<<<g1, GEMM_THREADS,
             (GEMM_K * GEMM_MT + GEMM_K * GEMM_NT) * sizeof(float)>>>(
        hex, W, BT, T, B, V);

    gather_out<<<N, B * 16>>>(idxw, bias, out, N, T, B);
}

// round 5
// speedup vs baseline: 1.4563x; 1.4563x over previous
#include <cuda_runtime.h>
#include <cuda_fp16.h>
#include <cstdint>

// ---------------------------------------------------------------------------
// InflateHexToVertex, factored:
//   Z[j,t,b,v] = hex[b,t,:] @ W[j*D:(j+1)*D, :]   (mma.sync fp16 GEMM, f32 acc)
//   out[b,n,v] = bias[v] + sum_j (idx[n,j] >= 0) * Z[j, idx[n,j], b, v]
//
// Z stored fp16 (12.6 MB) -> L2-resident; gather is L2-bound (~86 us).
// GEMM uses baseline-PTX tensor ops (ldmatrix + mma.sync m16n8k16), since
// the harness's compute_103 PTX pass rejects sm_103a-only tcgen05.
// ---------------------------------------------------------------------------

__device__ __half g_Zh[3 * 512 * 32 * 128];

// SMEM: A tile [128 rows][128 halves] and B tile [128 k][128 n], both stored
// as 16 chunks of 8 halves per row, chunk index XOR-swizzled with (row & 7)
// so ldmatrix phases hit all banks.
#define OFF_A 0
#define OFF_B 32768
#define GEMM_SMEM 65536

__device__ __forceinline__ uint32_t smem_u32(const void* p) {
    uint32_t a;
    asm("{ .reg .u64 t; cvta.to.shared.u64 t, %1; cvt.u32.u64 %0, t; }"
        : "=r"(a) : "l"(p));
    return a;
}

// --- Z = hex(16384x128) @ W(384x128) via mma.sync ----------------------------
// Grid (BT/128, 3), 256 threads (8 warps). Warp w computes rows w*16..w*16+15
// of the 128x128 output tile; K=128 in 8 k16 steps.
__global__ void __launch_bounds__(256, 2)
gemm_z(const float* __restrict__ A, const float* __restrict__ W,
       int T, int B) {
    extern __shared__ char sm[];
    const uint32_t smb = smem_u32(sm);
    const int tid = threadIdx.x;
    const int wid = tid >> 5;
    const int lane = tid & 31;
    const int m0 = blockIdx.x * 128;
    const int j  = blockIdx.y;

    // ---- stage A tile: fp32 -> fp16, swizzled ------------------------------
    #pragma unroll
    for (int it = 0; it < 8; ++it) {
        int p   = it * 256 + tid;          // 2048 chunks
        int row = p >> 4;
        int c   = p & 15;
        const float* src = A + (size_t)(m0 + row) * 128 + c * 8;
        float4 f0 = *(const float4*)src;
        float4 f1 = *(const float4*)(src + 4);
        __half2 h[4] = {__floats2half2_rn(f0.x, f0.y), __floats2half2_rn(f0.z, f0.w),
                        __floats2half2_rn(f1.x, f1.y), __floats2half2_rn(f1.z, f1.w)};
        *(uint4*)(sm + OFF_A + row * 256 + ((c ^ (row & 7)) << 4)) = *(uint4*)h;
    }
    // ---- stage B tile: W[j*128 + k][v], fp32 -> fp16, swizzled --------------
    #pragma unroll
    for (int it = 0; it < 8; ++it) {
        int p  = it * 256 + tid;
        int k  = p >> 4;
        int cn = p & 15;
        const float* src = W + ((size_t)j * 128 + k) * 128 + cn * 8;
        float4 f0 = *(const float4*)src;
        float4 f1 = *(const float4*)(src + 4);
        __half2 h[4] = {__floats2half2_rn(f0.x, f0.y), __floats2half2_rn(f0.z, f0.w),
                        __floats2half2_rn(f1.x, f1.y), __floats2half2_rn(f1.z, f1.w)};
        *(uint4*)(sm + OFF_B + k * 256 + ((cn ^ (k & 7)) << 4)) = *(uint4*)h;
    }
    __syncthreads();

    // ---- mainloop ------------------------------------------------------------
    float c[16][4];
    #pragma unroll
    for (int nb = 0; nb < 16; ++nb)
        #pragma unroll
        for (int q = 0; q < 4; ++q) c[nb][q] = 0.f;

    // ldmatrix lane addressing (see fragment layouts for m16n8k16):
    // A x4:  row = w*16 + (lane&15), chunk = 2*kb + (lane>>4)
    // B x2t: krow = kb*16 + (lane&15), chunk = nb           (lanes 16-31 unused)
    const int arow = wid * 16 + (lane & 15);
    const uint32_t a_base = smb + OFF_A + arow * 256;
    const int a_hi = lane >> 4;          // 0/1 -> +1 chunk
    const int a_r7 = arow & 7;
    const uint32_t b_base = smb + OFF_B + (lane & 15) * 256;
    const int b_r7 = lane & 7;

    #pragma unroll
    for (int kb = 0; kb < 8; ++kb) {
        uint32_t a0, a1, a2, a3;
        uint32_t a_addr = a_base + (((2 * kb + a_hi) ^ a_r7) << 4);
        asm volatile("ldmatrix.sync.aligned.m8n8.x4.shared.b16 {%0,%1,%2,%3}, [%4];"
                     : "=r"(a0), "=r"(a1), "=r"(a2), "=r"(a3) : "r"(a_addr));
        #pragma unroll
        for (int nb = 0; nb < 16; ++nb) {
            uint32_t b0, b1;
            uint32_t b_addr = b_base + kb * 4096 + ((nb ^ b_r7) << 4);
            asm volatile("ldmatrix.sync.aligned.m8n8.x2.trans.shared.b16 {%0,%1}, [%2];"
                         : "=r"(b0), "=r"(b1) : "r"(b_addr));
            asm volatile(
                "mma.sync.aligned.m16n8k16.row.col.f32.f16.f16.f32 "
                "{%0,%1,%2,%3}, {%4,%5,%6,%7}, {%8,%9}, {%0,%1,%2,%3};"
                : "+f"(c[nb][0]), "+f"(c[nb][1]), "+f"(c[nb][2]), "+f"(c[nb][3])
                : "r"(a0), "r"(a1), "r"(a2), "r"(a3), "r"(b0), "r"(b1));
        }
    }

    // ---- epilogue: cvt fp16, write Z[j][t][b][v] -----------------------------
    // c-frag: rows (lane>>2) and (lane>>2)+8 of the warp's 16; cols nb*8+(lane&3)*2
    const int r  = lane >> 2;
    const int q2 = (lane & 3) * 2;
    const int mA = m0 + wid * 16 + r;
    const int mB = mA + 8;
    const int bA = mA / T, tA = mA - bA * T;
    const int bB = mB / T, tB = mB - bB * T;
    __half* dstA = g_Zh + (((size_t)j * T + tA) * B + bA) * 128 + q2;
    __half* dstB = g_Zh + (((size_t)j * T + tB) * B + bB) * 128 + q2;
    #pragma unroll
    for (int nb = 0; nb < 16; ++nb) {
        *(__half2*)(dstA + nb * 8) = __floats2half2_rn(c[nb][0], c[nb][1]);
        *(__half2*)(dstB + nb * 8) = __floats2half2_rn(c[nb][2], c[nb][3]);
    }
}

// --- out[b,n,:] = bias + sum_j Z[j, idx[n,j], b, :] --------------------------
// R2 configuration (256 threads, 2 items/thread): measured 86.5 us.
__global__ void gather_out(const int* __restrict__ idxw,
                           const float* __restrict__ bias,
                           float* __restrict__ out, int N, int T, int B) {
    __shared__ int sh_t[3];
    const int n = blockIdx.x;

    if (threadIdx.x < 32) {
        // int64 little-endian => every odd word is the sign extension of the
        // preceding word; int32 data with values in [-1,T) fails w.p. ~1.
        int lo = idxw[2 * threadIdx.x];
        int hi = idxw[2 * threadIdx.x + 1];
        unsigned ok = __ballot_sync(0xffffffffu, hi == ((lo < 0) ? -1 : 0));
        int s = 1 + (ok == 0xffffffffu);
        if (threadIdx.x < 3) sh_t[threadIdx.x] = idxw[n * 3 * s + threadIdx.x * s];
    }
    __syncthreads();
    const int t0 = sh_t[0], t1 = sh_t[1], t2 = sh_t[2];

    const uint4*  Z16 = (const uint4*)g_Zh;
    const float4* b4  = (const float4*)bias;

    const int total = B * 16;
    for (int p = threadIdx.x; p < total; p += blockDim.x) {
        int b  = p >> 4;
        int v8 = p & 15;

        float4 accA = __ldg(b4 + v8 * 2);
        float4 accB = __ldg(b4 + v8 * 2 + 1);

        #pragma unroll
        for (int j = 0; j < 3; ++j) {
            int t = (j == 0) ? t0 : (j == 1) ? t1 : t2;
            if (t < 0) continue;
            uint4 z = Z16[(((size_t)j * T + t) * B + b) * 16 + v8];
            float2 f0 = __half22float2(*(__half2*)&z.x);
            float2 f1 = __half22float2(*(__half2*)&z.y);
            float2 f2 = __half22float2(*(__half2*)&z.z);
            float2 f3 = __half22float2(*(__half2*)&z.w);
            accA.x += f0.x; accA.y += f0.y; accA.z += f1.x; accA.w += f1.y;
            accB.x += f2.x; accB.y += f2.y; accB.z += f3.x; accB.w += f3.y;
        }

        float* o = out + ((size_t)b * N + n) * 128 + v8 * 8;
        __stcs((float4*)o, accA);
        __stcs((float4*)(o + 4), accB);
    }
}

extern "C" void kernel_launch(void* const* d_in, const int* in_sizes, int n_in,
                              void* d_out, int out_size) {
    const float* hex  = (const float*)d_in[0];   // (B, T, D) f32
    const int*   idxw = (const int*)d_in[1];     // (N, 3) int32 or int64
    const float* W    = (const float*)d_in[2];   // (3D, V) f32
    const float* bias = (const float*)d_in[3];   // (V,) f32
    float*       out  = (float*)d_out;           // (B, N, V) f32

    const int V      = in_sizes[3];              // 128
    const int threeD = in_sizes[2] / V;          // 384
    const int D      = threeD / 3;               // 128
    const int BT     = in_sizes[0] / D;          // B*T = 16384
    const int N      = in_sizes[1] / 3;          // 20000
    const int B      = out_size / (N * V);       // 32
    const int T      = BT / B;                   // 512

    cudaFuncSetAttribute(gemm_z, cudaFuncAttributeMaxDynamicSharedMemorySize,
                         GEMM_SMEM);

    dim3 g1(BT / 128, 3);
    gemm_z<<<g1, 256, GEMM_SMEM>>>(hex, W, T, B);

    gather_out<<<N, 256>>>(idxw, bias, out, N, T, B);
}

// round 6
// speedup vs baseline: 1.4779x; 1.0148x over previous
#include <cuda_runtime.h>
#include <cuda_fp16.h>
#include <cstdint>

// ---------------------------------------------------------------------------
// InflateHexToVertex, factored:
//   Z[j,t,b,v] = hex[b,t,:] @ W[j*D:(j+1)*D, :]   (mma.sync fp16 GEMM, f32 acc)
//   out[b,n,v] = bias[v] + sum_j (idx[n,j] >= 0) * Z[j, idx[n,j], b, v]
//
// Z stored fp16 (12.6 MB) -> L2-resident; gather is L2-bound.
// Gather processes 2 vertices per block with all 6 Z loads in flight (MLP),
// halving per-block overhead vs 1 vertex/block.
// ---------------------------------------------------------------------------

__device__ __half g_Zh[3 * 512 * 32 * 128];

#define OFF_A 0
#define OFF_B 32768
#define GEMM_SMEM 65536

__device__ __forceinline__ uint32_t smem_u32(const void* p) {
    uint32_t a;
    asm("{ .reg .u64 t; cvta.to.shared.u64 t, %1; cvt.u32.u64 %0, t; }"
        : "=r"(a) : "l"(p));
    return a;
}

// --- Z = hex(16384x128) @ W(384x128) via mma.sync ----------------------------
// Grid (BT/128, 3), 256 threads (8 warps). Warp w computes rows w*16..w*16+15
// of the 128x128 output tile; K=128 in 8 k16 steps.  (R5: measured ~10 us.)
__global__ void __launch_bounds__(256, 2)
gemm_z(const float* __restrict__ A, const float* __restrict__ W,
       int T, int B) {
    extern __shared__ char sm[];
    const uint32_t smb = smem_u32(sm);
    const int tid = threadIdx.x;
    const int wid = tid >> 5;
    const int lane = tid & 31;
    const int m0 = blockIdx.x * 128;
    const int j  = blockIdx.y;

    // ---- stage A tile: fp32 -> fp16, swizzled ------------------------------
    #pragma unroll
    for (int it = 0; it < 8; ++it) {
        int p   = it * 256 + tid;          // 2048 chunks
        int row = p >> 4;
        int c   = p & 15;
        const float* src = A + (size_t)(m0 + row) * 128 + c * 8;
        float4 f0 = *(const float4*)src;
        float4 f1 = *(const float4*)(src + 4);
        __half2 h[4] = {__floats2half2_rn(f0.x, f0.y), __floats2half2_rn(f0.z, f0.w),
                        __floats2half2_rn(f1.x, f1.y), __floats2half2_rn(f1.z, f1.w)};
        *(uint4*)(sm + OFF_A + row * 256 + ((c ^ (row & 7)) << 4)) = *(uint4*)h;
    }
    // ---- stage B tile: W[j*128 + k][v], fp32 -> fp16, swizzled --------------
    #pragma unroll
    for (int it = 0; it < 8; ++it) {
        int p  = it * 256 + tid;
        int k  = p >> 4;
        int cn = p & 15;
        const float* src = W + ((size_t)j * 128 + k) * 128 + cn * 8;
        float4 f0 = *(const float4*)src;
        float4 f1 = *(const float4*)(src + 4);
        __half2 h[4] = {__floats2half2_rn(f0.x, f0.y), __floats2half2_rn(f0.z, f0.w),
                        __floats2half2_rn(f1.x, f1.y), __floats2half2_rn(f1.z, f1.w)};
        *(uint4*)(sm + OFF_B + k * 256 + ((cn ^ (k & 7)) << 4)) = *(uint4*)h;
    }
    __syncthreads();

    // ---- mainloop ------------------------------------------------------------
    float c[16][4];
    #pragma unroll
    for (int nb = 0; nb < 16; ++nb)
        #pragma unroll
        for (int q = 0; q < 4; ++q) c[nb][q] = 0.f;

    const int arow = wid * 16 + (lane & 15);
    const uint32_t a_base = smb + OFF_A + arow * 256;
    const int a_hi = lane >> 4;
    const int a_r7 = arow & 7;
    const uint32_t b_base = smb + OFF_B + (lane & 15) * 256;
    const int b_r7 = lane & 7;

    #pragma unroll
    for (int kb = 0; kb < 8; ++kb) {
        uint32_t a0, a1, a2, a3;
        uint32_t a_addr = a_base + (((2 * kb + a_hi) ^ a_r7) << 4);
        asm volatile("ldmatrix.sync.aligned.m8n8.x4.shared.b16 {%0,%1,%2,%3}, [%4];"
                     : "=r"(a0), "=r"(a1), "=r"(a2), "=r"(a3) : "r"(a_addr));
        #pragma unroll
        for (int nb = 0; nb < 16; ++nb) {
            uint32_t b0, b1;
            uint32_t b_addr = b_base + kb * 4096 + ((nb ^ b_r7) << 4);
            asm volatile("ldmatrix.sync.aligned.m8n8.x2.trans.shared.b16 {%0,%1}, [%2];"
                         : "=r"(b0), "=r"(b1) : "r"(b_addr));
            asm volatile(
                "mma.sync.aligned.m16n8k16.row.col.f32.f16.f16.f32 "
                "{%0,%1,%2,%3}, {%4,%5,%6,%7}, {%8,%9}, {%0,%1,%2,%3};"
                : "+f"(c[nb][0]), "+f"(c[nb][1]), "+f"(c[nb][2]), "+f"(c[nb][3])
                : "r"(a0), "r"(a1), "r"(a2), "r"(a3), "r"(b0), "r"(b1));
        }
    }

    // ---- epilogue: cvt fp16, write Z[j][t][b][v] -----------------------------
    const int r  = lane >> 2;
    const int q2 = (lane & 3) * 2;
    const int mA = m0 + wid * 16 + r;
    const int mB = mA + 8;
    const int bA = mA / T, tA = mA - bA * T;
    const int bB = mB / T, tB = mB - bB * T;
    __half* dstA = g_Zh + (((size_t)j * T + tA) * B + bA) * 128 + q2;
    __half* dstB = g_Zh + (((size_t)j * T + tB) * B + bB) * 128 + q2;
    #pragma unroll
    for (int nb = 0; nb < 16; ++nb) {
        *(__half2*)(dstA + nb * 8) = __floats2half2_rn(c[nb][0], c[nb][1]);
        *(__half2*)(dstB + nb * 8) = __floats2half2_rn(c[nb][2], c[nb][3]);
    }
}

// --- out[b,n,:] = bias + sum_j Z[j, idx[n,j], b, :] --------------------------
// 2 vertices per block, 256 threads, 2 (b,v8) items per thread per vertex.
// All 6 Z loads per item issued back-to-back for MLP.
__global__ void gather_out(const int* __restrict__ idxw,
                           const float* __restrict__ bias,
                           float* __restrict__ out, int N, int T, int B) {
    __shared__ int sh_t[6];
    const int n0 = blockIdx.x * 2;

    if (threadIdx.x < 32) {
        // int64 little-endian => every odd word is the sign extension of the
        // preceding word; int32 data with values in [-1,T) fails w.p. ~1.
        int lo = idxw[2 * threadIdx.x];
        int hi = idxw[2 * threadIdx.x + 1];
        unsigned ok = __ballot_sync(0xffffffffu, hi == ((lo < 0) ? -1 : 0));
        int s = 1 + (ok == 0xffffffffu);
        if (threadIdx.x < 6) sh_t[threadIdx.x] = idxw[(n0 * 3 + threadIdx.x) * s];
    }
    __syncthreads();

    int tt[6];
    #pragma unroll
    for (int i = 0; i < 6; ++i) tt[i] = sh_t[i];

    const uint4*  Z16 = (const uint4*)g_Zh;
    const float4* b4  = (const float4*)bias;
    const uint4   zz  = make_uint4(0u, 0u, 0u, 0u);

    const int total = B * 16;                 // 512 items per vertex
    for (int p = threadIdx.x; p < total; p += blockDim.x) {
        const int b  = p >> 4;
        const int v8 = p & 15;
        const size_t rowoff = (size_t)b * 16 + v8;

        // Issue all 6 loads (3 per vertex) before any accumulation.
        uint4 z[6];
        #pragma unroll
        for (int i = 0; i < 6; ++i) {
            int j = i % 3;
            int t = tt[i];
            z[i] = (t >= 0)
                 ? Z16[((size_t)j * T + t) * (B * 16) + rowoff]
                 : zz;
        }

        float4 bsA = __ldg(b4 + v8 * 2);
        float4 bsB = __ldg(b4 + v8 * 2 + 1);

        #pragma unroll
        for (int nn = 0; nn < 2; ++nn) {
            float4 accA = bsA, accB = bsB;
            #pragma unroll
            for (int j = 0; j < 3; ++j) {
                uint4 zv = z[nn * 3 + j];
                float2 f0 = __half22float2(*(__half2*)&zv.x);
                float2 f1 = __half22float2(*(__half2*)&zv.y);
                float2 f2 = __half22float2(*(__half2*)&zv.z);
                float2 f3 = __half22float2(*(__half2*)&zv.w);
                accA.x += f0.x; accA.y += f0.y; accA.z += f1.x; accA.w += f1.y;
                accB.x += f2.x; accB.y += f2.y; accB.z += f3.x; accB.w += f3.y;
            }
            float* o = out + ((size_t)b * N + (n0 + nn)) * 128 + v8 * 8;
            __stcs((float4*)o, accA);
            __stcs((float4*)(o + 4), accB);
        }
    }
}

extern "C" void kernel_launch(void* const* d_in, const int* in_sizes, int n_in,
                              void* d_out, int out_size) {
    const float* hex  = (const float*)d_in[0];   // (B, T, D) f32
    const int*   idxw = (const int*)d_in[1];     // (N, 3) int32 or int64
    const float* W    = (const float*)d_in[2];   // (3D, V) f32
    const float* bias = (const float*)d_in[3];   // (V,) f32
    float*       out  = (float*)d_out;           // (B, N, V) f32

    const int V      = in_sizes[3];              // 128
    const int threeD = in_sizes[2] / V;          // 384
    const int D      = threeD / 3;               // 128
    const int BT     = in_sizes[0] / D;          // B*T = 16384
    const int N      = in_sizes[1] / 3;          // 20000
    const int B      = out_size / (N * V);       // 32
    const int T      = BT / B;                   // 512

    cudaFuncSetAttribute(gemm_z, cudaFuncAttributeMaxDynamicSharedMemorySize,
                         GEMM_SMEM);

    dim3 g1(BT / 128, 3);
    gemm_z<<<g1, 256, GEMM_SMEM>>>(hex, W, T, B);

    gather_out<<<N / 2, 256>>>(idxw, bias, out, N, T, B);
}

// round 7
// speedup vs baseline: 1.4887x; 1.0073x over previous
#include <cuda_runtime.h>
#include <cuda_fp16.h>
#include <cstdint>

// ---------------------------------------------------------------------------
// InflateHexToVertex, factored:
//   Z[j,t,b,v] = hex[b,t,:] @ W[j*D:(j+1)*D, :]   (mma.sync fp16 GEMM, f32 acc)
//   out[b,n,v] = bias[v] + sum_j (idx[n,j] >= 0) * Z[j, idx[n,j], b, v]
//
// Z stored fp16 (12.6 MB) -> L2-resident. Gather reads Z with ld.global.cg
// (L2-only, no L1 fill: Z can never be L1-resident, the fill was pure
// overhead and L1tex was the hottest unit at 74.6%).
// ---------------------------------------------------------------------------

__device__ __half g_Zh[3 * 512 * 32 * 128];

#define OFF_A 0
#define OFF_B 32768
#define GEMM_SMEM 65536

__device__ __forceinline__ uint32_t smem_u32(const void* p) {
    uint32_t a;
    asm("{ .reg .u64 t; cvta.to.shared.u64 t, %1; cvt.u32.u64 %0, t; }"
        : "=r"(a) : "l"(p));
    return a;
}

// --- Z = hex(16384x128) @ W(384x128) via mma.sync ----------------------------
// Grid (BT/128, 3), 256 threads (8 warps). Warp w computes rows w*16..w*16+15
// of the 128x128 output tile; K=128 in 8 k16 steps.  (measured ~11.5 us.)
__global__ void __launch_bounds__(256, 2)
gemm_z(const float* __restrict__ A, const float* __restrict__ W,
       int T, int B) {
    extern __shared__ char sm[];
    const uint32_t smb = smem_u32(sm);
    const int tid = threadIdx.x;
    const int wid = tid >> 5;
    const int lane = tid & 31;
    const int m0 = blockIdx.x * 128;
    const int j  = blockIdx.y;

    // ---- stage A tile: fp32 -> fp16, swizzled ------------------------------
    #pragma unroll
    for (int it = 0; it < 8; ++it) {
        int p   = it * 256 + tid;          // 2048 chunks
        int row = p >> 4;
        int c   = p & 15;
        const float* src = A + (size_t)(m0 + row) * 128 + c * 8;
        float4 f0 = *(const float4*)src;
        float4 f1 = *(const float4*)(src + 4);
        __half2 h[4] = {__floats2half2_rn(f0.x, f0.y), __floats2half2_rn(f0.z, f0.w),
                        __floats2half2_rn(f1.x, f1.y), __floats2half2_rn(f1.z, f1.w)};
        *(uint4*)(sm + OFF_A + row * 256 + ((c ^ (row & 7)) << 4)) = *(uint4*)h;
    }
    // ---- stage B tile: W[j*128 + k][v], fp32 -> fp16, swizzled --------------
    #pragma unroll
    for (int it = 0; it < 8; ++it) {
        int p  = it * 256 + tid;
        int k  = p >> 4;
        int cn = p & 15;
        const float* src = W + ((size_t)j * 128 + k) * 128 + cn * 8;
        float4 f0 = *(const float4*)src;
        float4 f1 = *(const float4*)(src + 4);
        __half2 h[4] = {__floats2half2_rn(f0.x, f0.y), __floats2half2_rn(f0.z, f0.w),
                        __floats2half2_rn(f1.x, f1.y), __floats2half2_rn(f1.z, f1.w)};
        *(uint4*)(sm + OFF_B + k * 256 + ((cn ^ (k & 7)) << 4)) = *(uint4*)h;
    }
    __syncthreads();

    // ---- mainloop ------------------------------------------------------------
    float c[16][4];
    #pragma unroll
    for (int nb = 0; nb < 16; ++nb)
        #pragma unroll
        for (int q = 0; q < 4; ++q) c[nb][q] = 0.f;

    const int arow = wid * 16 + (lane & 15);
    const uint32_t a_base = smb + OFF_A + arow * 256;
    const int a_hi = lane >> 4;
    const int a_r7 = arow & 7;
    const uint32_t b_base = smb + OFF_B + (lane & 15) * 256;
    const int b_r7 = lane & 7;

    #pragma unroll
    for (int kb = 0; kb < 8; ++kb) {
        uint32_t a0, a1, a2, a3;
        uint32_t a_addr = a_base + (((2 * kb + a_hi) ^ a_r7) << 4);
        asm volatile("ldmatrix.sync.aligned.m8n8.x4.shared.b16 {%0,%1,%2,%3}, [%4];"
                     : "=r"(a0), "=r"(a1), "=r"(a2), "=r"(a3) : "r"(a_addr));
        #pragma unroll
        for (int nb = 0; nb < 16; ++nb) {
            uint32_t b0, b1;
            uint32_t b_addr = b_base + kb * 4096 + ((nb ^ b_r7) << 4);
            asm volatile("ldmatrix.sync.aligned.m8n8.x2.trans.shared.b16 {%0,%1}, [%2];"
                         : "=r"(b0), "=r"(b1) : "r"(b_addr));
            asm volatile(
                "mma.sync.aligned.m16n8k16.row.col.f32.f16.f16.f32 "
                "{%0,%1,%2,%3}, {%4,%5,%6,%7}, {%8,%9}, {%0,%1,%2,%3};"
                : "+f"(c[nb][0]), "+f"(c[nb][1]), "+f"(c[nb][2]), "+f"(c[nb][3])
                : "r"(a0), "r"(a1), "r"(a2), "r"(a3), "r"(b0), "r"(b1));
        }
    }

    // ---- epilogue: cvt fp16, write Z[j][t][b][v] -----------------------------
    const int r  = lane >> 2;
    const int q2 = (lane & 3) * 2;
    const int mA = m0 + wid * 16 + r;
    const int mB = mA + 8;
    const int bA = mA / T, tA = mA - bA * T;
    const int bB = mB / T, tB = mB - bB * T;
    __half* dstA = g_Zh + (((size_t)j * T + tA) * B + bA) * 128 + q2;
    __half* dstB = g_Zh + (((size_t)j * T + tB) * B + bB) * 128 + q2;
    #pragma unroll
    for (int nb = 0; nb < 16; ++nb) {
        *(__half2*)(dstA + nb * 8) = __floats2half2_rn(c[nb][0], c[nb][1]);
        *(__half2*)(dstB + nb * 8) = __floats2half2_rn(c[nb][2], c[nb][3]);
    }
}

// --- out[b,n,:] = bias + sum_j Z[j, idx[n,j], b, :] --------------------------
// 2 vertices per block, 256 threads, 2 (b,v8) items per thread per vertex.
// All 6 Z loads issued back-to-back via ld.global.cg (L2-only).
__global__ void gather_out(const int* __restrict__ idxw,
                           const float* __restrict__ bias,
                           float* __restrict__ out, int N, int T, int B) {
    __shared__ int sh_t[6];
    const int n0 = blockIdx.x * 2;

    if (threadIdx.x < 32) {
        // int64 little-endian => every odd word is the sign extension of the
        // preceding word; int32 data with values in [-1,T) fails w.p. ~1.
        int lo = idxw[2 * threadIdx.x];
        int hi = idxw[2 * threadIdx.x + 1];
        unsigned ok = __ballot_sync(0xffffffffu, hi == ((lo < 0) ? -1 : 0));
        int s = 1 + (ok == 0xffffffffu);
        if (threadIdx.x < 6) sh_t[threadIdx.x] = idxw[(n0 * 3 + threadIdx.x) * s];
    }
    __syncthreads();

    int tt[6];
    #pragma unroll
    for (int i = 0; i < 6; ++i) tt[i] = sh_t[i];

    const uint4*  Z16 = (const uint4*)g_Zh;
    const float4* b4  = (const float4*)bias;
    const uint4   zz  = make_uint4(0u, 0u, 0u, 0u);

    const int total = B * 16;                 // 512 items per vertex
    for (int p = threadIdx.x; p < total; p += blockDim.x) {
        const int b  = p >> 4;
        const int v8 = p & 15;
        const size_t rowoff = (size_t)b * 16 + v8;

        // Issue all 6 loads (3 per vertex) before any accumulation; L2-only.
        uint4 z[6];
        #pragma unroll
        for (int i = 0; i < 6; ++i) {
            int j = i % 3;
            int t = tt[i];
            z[i] = (t >= 0)
                 ? __ldcg(Z16 + ((size_t)j * T + t) * (B * 16) + rowoff)
                 : zz;
        }

        float4 bsA = __ldg(b4 + v8 * 2);
        float4 bsB = __ldg(b4 + v8 * 2 + 1);

        #pragma unroll
        for (int nn = 0; nn < 2; ++nn) {
            float4 accA = bsA, accB = bsB;
            #pragma unroll
            for (int j = 0; j < 3; ++j) {
                uint4 zv = z[nn * 3 + j];
                float2 f0 = __half22float2(*(__half2*)&zv.x);
                float2 f1 = __half22float2(*(__half2*)&zv.y);
                float2 f2 = __half22float2(*(__half2*)&zv.z);
                float2 f3 = __half22float2(*(__half2*)&zv.w);
                accA.x += f0.x; accA.y += f0.y; accA.z += f1.x; accA.w += f1.y;
                accB.x += f2.x; accB.y += f2.y; accB.z += f3.x; accB.w += f3.y;
            }
            float* o = out + ((size_t)b * N + (n0 + nn)) * 128 + v8 * 8;
            __stcs((float4*)o, accA);
            __stcs((float4*)(o + 4), accB);
        }
    }
}

extern "C" void kernel_launch(void* const* d_in, const int* in_sizes, int n_in,
                              void* d_out, int out_size) {
    const float* hex  = (const float*)d_in[0];   // (B, T, D) f32
    const int*   idxw = (const int*)d_in[1];     // (N, 3) int32 or int64
    const float* W    = (const float*)d_in[2];   // (3D, V) f32
    const float* bias = (const float*)d_in[3];   // (V,) f32
    float*       out  = (float*)d_out;           // (B, N, V) f32

    const int V      = in_sizes[3];              // 128
    const int threeD = in_sizes[2] / V;          // 384
    const int D      = threeD / 3;               // 128
    const int BT     = in_sizes[0] / D;          // B*T = 16384
    const int N      = in_sizes[1] / 3;          // 20000
    const int B      = out_size / (N * V);       // 32
    const int T      = BT / B;                   // 512

    cudaFuncSetAttribute(gemm_z, cudaFuncAttributeMaxDynamicSharedMemorySize,
                         GEMM_SMEM);

    dim3 g1(BT / 128, 3);
    gemm_z<<<g1, 256, GEMM_SMEM>>>(hex, W, T, B);

    gather_out<<<N / 2, 256>>>(idxw, bias, out, N, T, B);
}